// round 8
// baseline (speedup 1.0000x reference)
#include <cuda_runtime.h>
#include <cuda_bf16.h>
#include <cuda_fp16.h>
#include <cstdint>

// PowerSoftmax attention via warp-level mma.sync (HMMA) — base sm_103 PTX.
//   S = (Q K^T)/8 ; P = S^2 ; O = (P / (rowsum(P)+1e-6)) V
// 64 heads of [2048, 64] fp32.
//
// QK^T: bf16 hi/lo split, 3 cross terms  (S rel err ~3e-5)
// P V : fp16 P x fp16 V (hi only)        (O rel err ~3e-4 total)
// Q A-fragments live in registers for the whole kv sweep.
// K/V staged raw (fp32) via cp.async: global latency hides under the
// previous tile's MMA work; the convert phase reads smem only.

#define NQ       2048
#define DDIM     64
#define BM       128
#define BKV      128
#define NITER    (NQ / BKV)
#define NTHREADS 256

// smem layout (bytes)
#define OFF_KHI  0            // converted K hi  [128 x 64 bf16]   16 KB
#define OFF_KLO  16384        // converted K lo                     16 KB
#define OFF_VH   32768        // Vt[d][kv] fp16 hi [64 x 256B]      16 KB
#define OFF_KRAW 49152        // staging K raw fp32 [128 x 64]      32 KB
#define OFF_VRAW 81920        // staging V raw fp32 [128 x 64]      32 KB
#define SMEM_BYTES 114688     // 112 KB -> 2 CTAs/SM
// Q prologue borrows OFF_KHI/OFF_KLO before the kv loop starts.

// [rows][64 x 2B = 128B] tiles (Q, K)
__device__ __forceinline__ uint32_t sw_q(int row, int cb) {
    return (uint32_t)(row * 128 + (cb ^ ((row & 7) << 4)));
}
// Vt tile: [64 rows][128 kv x 2B = 256B]
__device__ __forceinline__ uint32_t sw_v(int row, int cb) {
    return (uint32_t)(row * 256 + (cb ^ ((row & 7) << 4)));
}

__device__ __forceinline__ void ldsm_x4(uint32_t* r, uint32_t addr) {
    asm volatile("ldmatrix.sync.aligned.m8n8.x4.shared.b16 {%0,%1,%2,%3}, [%4];"
                 : "=r"(r[0]), "=r"(r[1]), "=r"(r[2]), "=r"(r[3]) : "r"(addr));
}
__device__ __forceinline__ void mma_bf16(float* c, const uint32_t* a, const uint32_t* b) {
    asm volatile("mma.sync.aligned.m16n8k16.row.col.f32.bf16.bf16.f32 "
                 "{%0,%1,%2,%3}, {%4,%5,%6,%7}, {%8,%9}, {%0,%1,%2,%3};"
                 : "+f"(c[0]), "+f"(c[1]), "+f"(c[2]), "+f"(c[3])
                 : "r"(a[0]), "r"(a[1]), "r"(a[2]), "r"(a[3]), "r"(b[0]), "r"(b[1]));
}
__device__ __forceinline__ void mma_f16(float* c, const uint32_t* a, const uint32_t* b) {
    asm volatile("mma.sync.aligned.m16n8k16.row.col.f32.f16.f16.f32 "
                 "{%0,%1,%2,%3}, {%4,%5,%6,%7}, {%8,%9}, {%0,%1,%2,%3};"
                 : "+f"(c[0]), "+f"(c[1]), "+f"(c[2]), "+f"(c[3])
                 : "r"(a[0]), "r"(a[1]), "r"(a[2]), "r"(a[3]), "r"(b[0]), "r"(b[1]));
}
__device__ __forceinline__ void cp16(uint32_t dst, const void* src) {
    asm volatile("cp.async.cg.shared.global [%0], [%1], 16;" :: "r"(dst), "l"(src));
}
#define CP_COMMIT() asm volatile("cp.async.commit_group;" ::: "memory")
#define CP_WAIT0()  asm volatile("cp.async.wait_group 0;" ::: "memory")

__global__ __launch_bounds__(NTHREADS, 2)
void power_attn_hmma(const float* __restrict__ Q, const float* __restrict__ K,
                     const float* __restrict__ V, float* __restrict__ O) {
    extern __shared__ char sm[];
    const uint32_t smb = (uint32_t)__cvta_generic_to_shared(sm);

    const int tid  = threadIdx.x;
    const int lane = tid & 31;
    const int wid  = tid >> 5;
    const int mr   = wid * 16;                 // warp's 16-row Q strip

    const size_t head = (size_t)blockIdx.y * NQ * DDIM;
    const float* qb = Q + head + (size_t)blockIdx.x * BM * DDIM;
    const float* kb = K + head;
    const float* vb = V + head;

    // ---- Prologue: stage K(0)/V(0) via cp.async; convert Q meanwhile ----
    #pragma unroll
    for (int p = 0; p < 8; ++p) {
        int idx = tid + p * NTHREADS;                       // 0..2047 16B chunks
        cp16(smb + OFF_KRAW + idx * 16, (const char*)kb + idx * 16);
        cp16(smb + OFF_VRAW + idx * 16, (const char*)vb + idx * 16);
    }
    CP_COMMIT();

    {   // Q -> bf16 hi/lo into (temporarily) OFF_KHI/OFF_KLO
        const float4* qg = (const float4*)qb;
        #pragma unroll
        for (int p = 0; p < 8; ++p) {
            int idx = tid + p * NTHREADS;
            int row = idx >> 4;
            int c8  = (idx & 15) * 8;
            float4 x = qg[idx];
            __nv_bfloat16 h0 = __float2bfloat16(x.x), h1 = __float2bfloat16(x.y);
            __nv_bfloat16 h2 = __float2bfloat16(x.z), h3 = __float2bfloat16(x.w);
            __nv_bfloat16 l0 = __float2bfloat16(x.x - __bfloat162float(h0));
            __nv_bfloat16 l1 = __float2bfloat16(x.y - __bfloat162float(h1));
            __nv_bfloat16 l2 = __float2bfloat16(x.z - __bfloat162float(h2));
            __nv_bfloat16 l3 = __float2bfloat16(x.w - __bfloat162float(h3));
            uint32_t sw = sw_q(row, c8);
            uint2 hh, ll;
            hh.x = (uint32_t)__bfloat16_as_ushort(h1) << 16 | __bfloat16_as_ushort(h0);
            hh.y = (uint32_t)__bfloat16_as_ushort(h3) << 16 | __bfloat16_as_ushort(h2);
            ll.x = (uint32_t)__bfloat16_as_ushort(l1) << 16 | __bfloat16_as_ushort(l0);
            ll.y = (uint32_t)__bfloat16_as_ushort(l3) << 16 | __bfloat16_as_ushort(l2);
            *(uint2*)(sm + OFF_KHI + sw) = hh;
            *(uint2*)(sm + OFF_KLO + sw) = ll;
        }
    }
    __syncthreads();

    // ---- Hoist Q A-fragments for the whole kernel ----
    uint32_t Ah[4][4], Al[4][4];
    {
        const int a_row = mr + (lane & 15);
        const int a_cbo = (lane >> 4) << 4;          // +0 / +16B
        #pragma unroll
        for (int ks = 0; ks < 4; ++ks) {
            ldsm_x4(Ah[ks], smb + OFF_KHI + sw_q(a_row, ks * 32 + a_cbo));
            ldsm_x4(Al[ks], smb + OFF_KLO + sw_q(a_row, ks * 32 + a_cbo));
        }
    }

    float OC[8][4];
    #pragma unroll
    for (int d = 0; d < 8; ++d)
        #pragma unroll
        for (int r = 0; r < 4; ++r) OC[d][r] = 0.f;
    float rs0 = 0.f, rs1 = 0.f;                      // rowsum (rows l/4, l/4+8)

    // x4 B-fragment lane addressing (2 n-blocks per load)
    const int bx_row = (lane & 7) + ((lane >> 4) << 3);
    const int bx_cbo = ((lane >> 3) & 1) << 4;

    const int vpart = tid >> 6;                      // V convert: kv quarter
    const int vd    = tid & 63;

    for (int nt = 0; nt < NITER; ++nt) {
        CP_WAIT0();
        __syncthreads();     // staged data visible; prev tile consumed; Q hoisted

        // ---- Convert staged K -> bf16 hi/lo (smem -> smem) ----
        #pragma unroll
        for (int p = 0; p < 8; ++p) {
            int idx = tid + p * NTHREADS;
            int row = idx >> 4;
            int c8  = (idx & 15) * 8;
            float4 x = *(const float4*)(sm + OFF_KRAW + idx * 16);
            __nv_bfloat16 h0 = __float2bfloat16(x.x), h1 = __float2bfloat16(x.y);
            __nv_bfloat16 h2 = __float2bfloat16(x.z), h3 = __float2bfloat16(x.w);
            __nv_bfloat16 l0 = __float2bfloat16(x.x - __bfloat162float(h0));
            __nv_bfloat16 l1 = __float2bfloat16(x.y - __bfloat162float(h1));
            __nv_bfloat16 l2 = __float2bfloat16(x.z - __bfloat162float(h2));
            __nv_bfloat16 l3 = __float2bfloat16(x.w - __bfloat162float(h3));
            uint32_t sw = sw_q(row, c8);
            uint2 hh, ll;
            hh.x = (uint32_t)__bfloat16_as_ushort(h1) << 16 | __bfloat16_as_ushort(h0);
            hh.y = (uint32_t)__bfloat16_as_ushort(h3) << 16 | __bfloat16_as_ushort(h2);
            ll.x = (uint32_t)__bfloat16_as_ushort(l1) << 16 | __bfloat16_as_ushort(l0);
            ll.y = (uint32_t)__bfloat16_as_ushort(l3) << 16 | __bfloat16_as_ushort(l2);
            *(uint2*)(sm + OFF_KHI + sw) = hh;
            *(uint2*)(sm + OFF_KLO + sw) = ll;
        }

        // ---- Convert staged V -> Vt[d][kv] fp16 (hi only, transposed) ----
        #pragma unroll
        for (int i = 0; i < 8; ++i) {
            int kv = vpart * 32 + i * 4;
            const char* vr = sm + OFF_VRAW + vd * 4;
            float x0 = *(const float*)(vr + (size_t)(kv + 0) * 256);
            float x1 = *(const float*)(vr + (size_t)(kv + 1) * 256);
            float x2 = *(const float*)(vr + (size_t)(kv + 2) * 256);
            float x3 = *(const float*)(vr + (size_t)(kv + 3) * 256);
            __half2 ha = __floats2half2_rn(x0, x1);
            __half2 hb = __floats2half2_rn(x2, x3);
            uint2 u;
            u.x = *(uint32_t*)&ha;
            u.y = *(uint32_t*)&hb;
            *(uint2*)(sm + OFF_VH + sw_v(vd, kv * 2)) = u;
        }
        __syncthreads();

        // ---- Prefetch next tile into staging (hides under MMA below) ----
        if (nt + 1 < NITER) {
            const char* kn = (const char*)(kb + (size_t)(nt + 1) * BKV * DDIM);
            const char* vn = (const char*)(vb + (size_t)(nt + 1) * BKV * DDIM);
            #pragma unroll
            for (int p = 0; p < 8; ++p) {
                int idx = tid + p * NTHREADS;
                cp16(smb + OFF_KRAW + idx * 16, kn + idx * 16);
                cp16(smb + OFF_VRAW + idx * 16, vn + idx * 16);
            }
            CP_COMMIT();
        }

        #pragma unroll
        for (int h = 0; h < 2; ++h) {                // kv halves of 64
            // ---- QK^T: S[16 x 64] in C fragments ----
            float SC[8][4];
            #pragma unroll
            for (int nb = 0; nb < 8; ++nb)
                #pragma unroll
                for (int r = 0; r < 4; ++r) SC[nb][r] = 0.f;

            #pragma unroll
            for (int ks = 0; ks < 4; ++ks) {
                #pragma unroll
                for (int p = 0; p < 4; ++p) {        // n-block pairs
                    int n0 = h * 64 + p * 16;
                    uint32_t Bh[4], Bl[4];
                    ldsm_x4(Bh, smb + OFF_KHI + sw_q(n0 + bx_row, ks * 32 + bx_cbo));
                    ldsm_x4(Bl, smb + OFF_KLO + sw_q(n0 + bx_row, ks * 32 + bx_cbo));
                    mma_bf16(SC[2 * p],     Ah[ks], Bh + 0);
                    mma_bf16(SC[2 * p],     Ah[ks], Bl + 0);
                    mma_bf16(SC[2 * p],     Al[ks], Bh + 0);
                    mma_bf16(SC[2 * p + 1], Ah[ks], Bh + 2);
                    mma_bf16(SC[2 * p + 1], Ah[ks], Bl + 2);
                    mma_bf16(SC[2 * p + 1], Al[ks], Bh + 2);
                }
            }

            // ---- p = (s/8)^2, pack fp16 A-fragments, rowsum from rounded p ----
            uint32_t P[4][4];
            #pragma unroll
            for (int nb = 0; nb < 8; ++nb) {
                float s0 = SC[nb][0] * 0.125f, s1 = SC[nb][1] * 0.125f;
                float s2 = SC[nb][2] * 0.125f, s3 = SC[nb][3] * 0.125f;
                __half2 h01 = __floats2half2_rn(s0 * s0, s1 * s1);
                __half2 h23 = __floats2half2_rn(s2 * s2, s3 * s3);
                float2 f01 = __half22float2(h01);
                float2 f23 = __half22float2(h23);
                rs0 += f01.x + f01.y;
                rs1 += f23.x + f23.y;
                int kk = nb >> 1, hi = (nb & 1) * 2;
                P[kk][hi + 0] = *(uint32_t*)&h01;
                P[kk][hi + 1] = *(uint32_t*)&h23;
            }

            // ---- O += P V (fp16 hi) ----
            #pragma unroll
            for (int kk = 0; kk < 4; ++kk) {
                int kvb = (h * 64 + kk * 16) * 2 + bx_cbo;   // byte col in Vt row
                #pragma unroll
                for (int dp = 0; dp < 4; ++dp) {             // d-block pairs
                    uint32_t Bv[4];
                    ldsm_x4(Bv, smb + OFF_VH + sw_v(dp * 16 + bx_row, kvb));
                    mma_f16(OC[2 * dp],     P[kk], Bv + 0);
                    mma_f16(OC[2 * dp + 1], P[kk], Bv + 2);
                }
            }
        }
    }

    // ---- Rowsum reduce across the 4 lanes of each row group ----
    rs0 += __shfl_xor_sync(0xFFFFFFFF, rs0, 1);
    rs0 += __shfl_xor_sync(0xFFFFFFFF, rs0, 2);
    rs1 += __shfl_xor_sync(0xFFFFFFFF, rs1, 1);
    rs1 += __shfl_xor_sync(0xFFFFFFFF, rs1, 2);
    const float inv0 = 1.0f / (rs0 + 1e-6f);
    const float inv1 = 1.0f / (rs1 + 1e-6f);

    // ---- Store O ----
    {
        const int row0 = mr + (lane >> 2);
        float* ob = O + head + ((size_t)blockIdx.x * BM + row0) * DDIM;
        #pragma unroll
        for (int db = 0; db < 8; ++db) {
            int col = db * 8 + (lane & 3) * 2;
            float2 t0 = make_float2(OC[db][0] * inv0, OC[db][1] * inv0);
            float2 t1 = make_float2(OC[db][2] * inv1, OC[db][3] * inv1);
            *(float2*)(ob + col) = t0;
            *(float2*)(ob + 8 * DDIM + col) = t1;
        }
    }
}

extern "C" void kernel_launch(void* const* d_in, const int* in_sizes, int n_in,
                              void* d_out, int out_size) {
    const float* q = (const float*)d_in[0];
    const float* k = (const float*)d_in[1];
    const float* v = (const float*)d_in[2];
    float* o = (float*)d_out;

    const int BH = in_sizes[0] / (NQ * DDIM);   // 64 heads

    cudaFuncSetAttribute(power_attn_hmma,
                         cudaFuncAttributeMaxDynamicSharedMemorySize, SMEM_BYTES);

    dim3 grid(NQ / BM, BH);
    power_attn_hmma<<<grid, NTHREADS, SMEM_BYTES>>>(q, k, v, o);
}